// round 12
// baseline (speedup 1.0000x reference)
#include <cuda_runtime.h>
#include <cstdint>

// ---------------------------------------------------------------------------
// ConvLocalBlock via legacy mma.sync.m16n8k8 tf32 (PTX compute_103-safe; the
// harness's PTX target has no 'a' suffix so tcgen05/TMEM are unavailable).
//
// Stage 1: y = relu(bn1(x_patches @ conv_w))      M=130048 K=320  N=256
// Stage 2: z[:,l,:] = relu(bn2(y_win @ lw[l]))    per l: M=256 K=1280 N=256
//
// R11 change vs R10: the 32x64-warp design was CO-BOUND (crossbar 524 vs
// tensor 512 cyc per SM-k8, measured 845 -> ~60% both pipes). Move to
// CTA 256(M)x128(N), 8 warps as 4m x 2n of 64x64 warp tiles:
//   smem reads per 128x128-k8: 24KB -> 16KB  => crossbar ~362 cyc/SM-k8
//   tensor demand unchanged 512 cyc/SM-k8    => tensor-bound, 1.4x headroom
// acc = 128 regs/thread, 1 CTA/SM (256 thr, 256-reg budget), NSTAGE=4 ring
// (213KB SMEM) to keep pipeline slack at occupancy 1.
//
// Engine: raw-fp32-bits tf32 MMA (RZ truncation; product bias cancelled by
// TCORR in BN alpha), A fragments via ldmatrix.x4.b16, B scalar LDS with
// BSTR=136 (conflict-free).
// ---------------------------------------------------------------------------

#define FSZ   5
#define NB    256
#define LIN   512
#define CIN   64
#define UDIM  256
#define L1DIM 508
#define L2DIM 504
#define KCONV 320
#define KLOC  1280
#define BNEPS 0.001f
#define TCORR 1.0007045f              // cancels tf32 RZ-truncation product bias

#define NSTAGE  4
#define KC      32
#define AROWS   256                   // CTA M-tile
#define ASTR    36                    // A smem row stride (floats)
#define BSTR    136                   // B smem row stride (136%32==8: clean)
#define A_BYTES (AROWS * ASTR * 4)    // 36864
#define B_BYTES (KC * BSTR * 4)      // 17408
#define STAGE_BYTES (A_BYTES + B_BYTES) // 54272
#define SMEM_ALPHA  0
#define SMEM_BETA   512
#define SMEM_STAGE0 1024
#define SMEM_TOTAL  (SMEM_STAGE0 + NSTAGE * STAGE_BYTES)  // 218112 (213 KB)

__device__ __align__(128) float g_y[(size_t)NB * L1DIM * UDIM];

// ---- PTX helpers -----------------------------------------------------------
__device__ __forceinline__ uint32_t smem_u32(const void* p) {
    uint32_t a;
    asm("{ .reg .u64 t; cvta.to.shared.u64 t, %1; cvt.u32.u64 %0, t; }"
        : "=r"(a) : "l"(p));
    return a;
}
#define CP_ASYNC16(dst, src) \
    asm volatile("cp.async.cg.shared.global [%0], [%1], 16;" \
                 :: "r"(dst), "l"(src) : "memory")
#define CP_COMMIT() asm volatile("cp.async.commit_group;" ::: "memory")
#define CP_WAIT2()  asm volatile("cp.async.wait_group 2;" ::: "memory")

__device__ __forceinline__ void ldsm_x4(uint32_t* r, uint32_t addr) {
    asm volatile("ldmatrix.sync.aligned.m8n8.x4.shared.b16 {%0,%1,%2,%3}, [%4];"
                 : "=r"(r[0]), "=r"(r[1]), "=r"(r[2]), "=r"(r[3]) : "r"(addr));
}
__device__ __forceinline__ void mma8(float* d, const uint32_t* a, const uint32_t* b) {
    asm volatile("mma.sync.aligned.m16n8k8.row.col.f32.tf32.tf32.f32 "
                 "{%0,%1,%2,%3}, {%4,%5,%6,%7}, {%8,%9}, {%0,%1,%2,%3};"
                 : "+f"(d[0]), "+f"(d[1]), "+f"(d[2]), "+f"(d[3])
                 : "r"(a[0]), "r"(a[1]), "r"(a[2]), "r"(a[3]),
                   "r"(b[0]), "r"(b[1]));
}

// one pipeline-stage load: A 256 rows x 32 floats + B 32 k-rows x 128 n
__device__ __forceinline__ void load_stage(uint32_t sb, const float* const* aptr,
                                           const float* bsrc0, int tid) {
    const int achunk = tid & 7;
    const int bchunk = tid & 31;
    #pragma unroll
    for (int p = 0; p < 8; p++) {
        int arow = (tid >> 3) + p * 32;
        uint32_t adst = sb + (uint32_t)(arow * ASTR + achunk * 4) * 4;
        CP_ASYNC16(adst, aptr[p] + achunk * 4);
    }
    const uint32_t sbB = sb + A_BYTES;
    #pragma unroll
    for (int p = 0; p < 4; p++) {
        int brow = (tid >> 5) + p * 8;
        uint32_t bdst = sbB + (uint32_t)(brow * BSTR + bchunk * 4) * 4;
        CP_ASYNC16(bdst, bsrc0 + (size_t)brow * UDIM + bchunk * 4);
    }
}

// ---------------------------------------------------------------------------
// MODE 0: conv stage.  grid (508 m-tiles, 2 n-tiles).    A=x, out=g_y
// MODE 1: local stage. grid (1 m, 2 n, 504 l).           A=g_y, out=z
// ---------------------------------------------------------------------------
template <int MODE>
__global__ void __launch_bounds__(256, 1)
gemm_mma(const float* __restrict__ Ain, const float* __restrict__ Bmat0,
         const float* __restrict__ bias, const float* __restrict__ gg,
         const float* __restrict__ bbn, const float* __restrict__ mmn,
         const float* __restrict__ vvn, float* __restrict__ outp)
{
    extern __shared__ char smem[];
    const uint32_t sbase = smem_u32(smem);
    const uint32_t sb0 = sbase + SMEM_STAGE0;
    const int tid  = threadIdx.x;
    const int wid  = tid >> 5;
    const int lane = tid & 31;
    const int wm   = wid & 3;          // warp m index (0..3), 64 rows each
    const int wn   = wid >> 2;         // warp n index (0..1), 64 cols each
    const int g    = lane >> 2;
    const int tg   = lane & 3;

    const int S   = MODE ? (KLOC / KC) : (KCONV / KC);
    const int l   = MODE ? blockIdx.z : 0;
    const int mb0 = blockIdx.x * AROWS;
    const int n0  = blockIdx.y * 128;

    const float* Bmat = MODE ? (Bmat0 + (size_t)l * KLOC * UDIM) : Bmat0;
    float* out = MODE ? outp : g_y;

    // BN alpha/beta (alpha carries the tf32-truncation bias correction)
    if (tid < 128) {
        int n = n0 + tid;
        float a_ = gg[n] * rsqrtf(vvn[n] + BNEPS);
        float bi = MODE ? bias[(size_t)l * UDIM + n] : bias[n];
        ((float*)(smem + SMEM_ALPHA))[tid] = a_ * TCORR;
        ((float*)(smem + SMEM_BETA))[tid]  = bbn[n] + (bi - mmn[n]) * a_;
    }

    // per-thread A row pointers for the 8 load passes
    const float* aptr[8];
    #pragma unroll
    for (int p = 0; p < 8; p++) {
        int r = (tid >> 3) + p * 32;
        if (MODE) {
            aptr[p] = g_y + ((size_t)(mb0 + r) * L1DIM + l) * UDIM;
        } else {
            unsigned gm = mb0 + r;
            unsigned b  = gm / L1DIM;
            unsigned t  = gm - b * L1DIM;
            aptr[p] = Ain + ((size_t)b * LIN + t) * CIN;
        }
    }

    // pipeline prologue: stages 0..2
    #pragma unroll
    for (int p = 0; p < NSTAGE - 1; p++) {
        load_stage(sb0 + p * STAGE_BYTES, aptr, Bmat + (size_t)(p * KC) * UDIM + n0, tid);
        #pragma unroll
        for (int i = 0; i < 8; i++) aptr[i] += KC;
        CP_COMMIT();
    }

    float acc[4][8][4] = {};

    // ldmatrix lane->tile-row mapping for A fragments (4 m-frags of 16 rows)
    const int trow = (lane & 7) + ((lane >> 3) & 1) * 8;
    const int tk   = (lane >> 4) * 4;
    int a_lm_off[4];
    #pragma unroll
    for (int mf = 0; mf < 4; mf++)
        a_lm_off[mf] = (wm * 64 + mf * 16 + trow) * ASTR + tk;
    // scalar-B fragment base offset (floats)
    const int boff = tg * BSTR + wn * 64 + g;

    // Loop invariant: stage s = cp.async group s; committed before iter s's
    // wait = 3+s groups (0..s+2); wait_group(2) -> group s resident. The
    // single barrier proves compute s-1 done, protecting slot
    // (s+3)%4 == (s-1)%4 for the loads issued right after it.
    for (int s = 0; s < S; s++) {
        CP_WAIT2();
        __syncthreads();

        int pn = s + NSTAGE - 1;
        if (pn < S) {
            load_stage(sb0 + (pn % NSTAGE) * STAGE_BYTES, aptr,
                       Bmat + (size_t)(pn * KC) * UDIM + n0, tid);
            #pragma unroll
            for (int i = 0; i < 8; i++) aptr[i] += KC;
        }
        CP_COMMIT();          // uniform one group per iteration (may be empty)

        const uint32_t stg = sb0 + (s % NSTAGE) * STAGE_BYTES;
        const uint32_t* bB = (const uint32_t*)(smem + SMEM_STAGE0 +
                                               (s % NSTAGE) * STAGE_BYTES +
                                               A_BYTES) + boff;

        #pragma unroll
        for (int k8 = 0; k8 < KC / 8; k8++) {
            const int kk = k8 * 8;
            uint32_t af[4][4];
            #pragma unroll
            for (int mf = 0; mf < 4; mf++)
                ldsm_x4(af[mf], stg + (uint32_t)(a_lm_off[mf] + kk) * 4);
            uint32_t bf[8][2];
            #pragma unroll
            for (int jf = 0; jf < 8; jf++) {
                const uint32_t* p0 = bB + kk * BSTR + jf * 8;
                bf[jf][0] = p0[0];
                bf[jf][1] = p0[4 * BSTR];
            }
            #pragma unroll
            for (int mf = 0; mf < 4; mf++)
                #pragma unroll
                for (int jf = 0; jf < 8; jf++)
                    mma8(acc[mf][jf], af[mf], bf[jf]);
        }
    }

    // ---- epilogue: BN + ReLU, write out ----
    const float* al = (const float*)(smem + SMEM_ALPHA);
    const float* be = (const float*)(smem + SMEM_BETA);
    #pragma unroll
    for (int mf = 0; mf < 4; mf++) {
        int r0 = mb0 + wm * 64 + mf * 16 + g;   // and r0+8
        float* orow0;
        float* orow1;
        if (MODE) {
            orow0 = out + ((size_t)r0 * L2DIM + l) * UDIM;
            orow1 = out + ((size_t)(r0 + 8) * L2DIM + l) * UDIM;
        } else {
            orow0 = out + (size_t)r0 * UDIM;
            orow1 = out + (size_t)(r0 + 8) * UDIM;
        }
        #pragma unroll
        for (int jf = 0; jf < 8; jf++) {
            int cl = wn * 64 + jf * 8 + 2 * tg;
            float a0 = al[cl], a1 = al[cl + 1];
            float e0 = be[cl], e1 = be[cl + 1];
            float2 v0, v1;
            v0.x = fmaxf(acc[mf][jf][0] * a0 + e0, 0.f);
            v0.y = fmaxf(acc[mf][jf][1] * a1 + e1, 0.f);
            v1.x = fmaxf(acc[mf][jf][2] * a0 + e0, 0.f);
            v1.y = fmaxf(acc[mf][jf][3] * a1 + e1, 0.f);
            *(float2*)(orow0 + n0 + cl) = v0;
            *(float2*)(orow1 + n0 + cl) = v1;
        }
    }
}

// ---------------------------------------------------------------------------
extern "C" void kernel_launch(void* const* d_in, const int* in_sizes, int n_in,
                              void* d_out, int out_size)
{
    const float* x      = (const float*)d_in[0];
    const float* conv_w = (const float*)d_in[1];
    const float* conv_b = (const float*)d_in[2];
    const float* g1     = (const float*)d_in[3];
    const float* b1     = (const float*)d_in[4];
    const float* m1     = (const float*)d_in[5];
    const float* v1     = (const float*)d_in[6];
    const float* lw     = (const float*)d_in[7];
    const float* lb     = (const float*)d_in[8];
    const float* g2     = (const float*)d_in[9];
    const float* b2     = (const float*)d_in[10];
    const float* m2     = (const float*)d_in[11];
    const float* v2     = (const float*)d_in[12];
    float* z = (float*)d_out;

    static bool attr_set = false;
    if (!attr_set) {
        cudaFuncSetAttribute(gemm_mma<0>,
            cudaFuncAttributeMaxDynamicSharedMemorySize, SMEM_TOTAL);
        cudaFuncSetAttribute(gemm_mma<1>,
            cudaFuncAttributeMaxDynamicSharedMemorySize, SMEM_TOTAL);
        cudaFuncSetAttribute(gemm_mma<0>,
            cudaFuncAttributePreferredSharedMemoryCarveout, 100);
        cudaFuncSetAttribute(gemm_mma<1>,
            cudaFuncAttributePreferredSharedMemoryCarveout, 100);
        attr_set = true;
    }

    // Stage 1: M=130048 (508 tiles of 256), N=256 (2 tiles), K=320
    gemm_mma<0><<<dim3(508, 2, 1), 256, SMEM_TOTAL>>>(
        x, conv_w, conv_b, g1, b1, m1, v1, nullptr);

    // Stage 2: per-l GEMMs, M=256 (1 tile), N=256 (2 tiles), K=1280, l=504
    gemm_mma<1><<<dim3(1, 2, L2DIM), 256, SMEM_TOTAL>>>(
        nullptr, lw, lb, g2, b2, m2, v2, z);
}

// round 13
// speedup vs baseline: 1.0706x; 1.0706x over previous
#include <cuda_runtime.h>
#include <cstdint>

// ---------------------------------------------------------------------------
// ConvLocalBlock via legacy mma.sync.m16n8k8 tf32 (PTX compute_103-safe; the
// harness's PTX target has no 'a' suffix so tcgen05/TMEM are unavailable).
//
// Stage 1: y = relu(bn1(x_patches @ conv_w))      M=130048 K=320  N=256
// Stage 2: z[:,l,:] = relu(bn2(y_win @ lw[l]))    per l: M=256 K=1280 N=256
//
// R12 = merge of R10+R11 lessons:
//  * R11's 64x64 warp tiles cut smem fragment traffic (16KB vs 24KB per
//    128x128-k8) -> crossbar below tensor demand.    [keep]
//  * R11's 1 CTA/SM exposed barrier/wait latency (issue 17%, tensor 56%).
//    [fix] CTA shrunk to 128x128 with 4 warps (2m x 2n of 64x64), 128 thr,
//    NSTAGE=3 -> 108.5KB SMEM -> 2 CTAs/SM; co-resident CTAs interleave
//    barrier phases like R10 did.
//
// Engine: raw-fp32-bits tf32 MMA (RZ truncation; product bias cancelled by
// TCORR in BN alpha), A fragments via ldmatrix.x4.b16, B scalar LDS with
// BSTR=136 (conflict-free). Single barrier per k-stage.
// ---------------------------------------------------------------------------

#define FSZ   5
#define NB    256
#define LIN   512
#define CIN   64
#define UDIM  256
#define L1DIM 508
#define L2DIM 504
#define KCONV 320
#define KLOC  1280
#define BNEPS 0.001f
#define TCORR 1.0007045f              // cancels tf32 RZ-truncation product bias

#define NSTAGE  3
#define KC      32
#define AROWS   128                   // CTA M-tile
#define ASTR    36                    // A smem row stride (floats)
#define BSTR    136                   // B smem row stride (136%32==8: clean)
#define A_BYTES (AROWS * ASTR * 4)    // 18432
#define B_BYTES (KC * BSTR * 4)       // 17408
#define STAGE_BYTES (A_BYTES + B_BYTES) // 35840
#define SMEM_ALPHA  0
#define SMEM_BETA   512
#define SMEM_STAGE0 1024
#define SMEM_TOTAL  (SMEM_STAGE0 + NSTAGE * STAGE_BYTES)  // 108544 (106 KB)

__device__ __align__(128) float g_y[(size_t)NB * L1DIM * UDIM];

// ---- PTX helpers -----------------------------------------------------------
__device__ __forceinline__ uint32_t smem_u32(const void* p) {
    uint32_t a;
    asm("{ .reg .u64 t; cvta.to.shared.u64 t, %1; cvt.u32.u64 %0, t; }"
        : "=r"(a) : "l"(p));
    return a;
}
#define CP_ASYNC16(dst, src) \
    asm volatile("cp.async.cg.shared.global [%0], [%1], 16;" \
                 :: "r"(dst), "l"(src) : "memory")
#define CP_COMMIT() asm volatile("cp.async.commit_group;" ::: "memory")
#define CP_WAIT1()  asm volatile("cp.async.wait_group 1;" ::: "memory")

__device__ __forceinline__ void ldsm_x4(uint32_t* r, uint32_t addr) {
    asm volatile("ldmatrix.sync.aligned.m8n8.x4.shared.b16 {%0,%1,%2,%3}, [%4];"
                 : "=r"(r[0]), "=r"(r[1]), "=r"(r[2]), "=r"(r[3]) : "r"(addr));
}
__device__ __forceinline__ void mma8(float* d, const uint32_t* a, const uint32_t* b) {
    asm volatile("mma.sync.aligned.m16n8k8.row.col.f32.tf32.tf32.f32 "
                 "{%0,%1,%2,%3}, {%4,%5,%6,%7}, {%8,%9}, {%0,%1,%2,%3};"
                 : "+f"(d[0]), "+f"(d[1]), "+f"(d[2]), "+f"(d[3])
                 : "r"(a[0]), "r"(a[1]), "r"(a[2]), "r"(a[3]),
                   "r"(b[0]), "r"(b[1]));
}

// one pipeline-stage load (128 threads): A 128 rows x 32 floats + B 32 x 128
__device__ __forceinline__ void load_stage(uint32_t sb, const float* const* aptr,
                                           const float* bsrc0, int tid) {
    const int achunk = tid & 7;        // 16B chunk within A row
    const int bchunk = tid & 31;       // 16B chunk within B row
    #pragma unroll
    for (int p = 0; p < 8; p++) {
        int arow = (tid >> 3) + p * 16;
        uint32_t adst = sb + (uint32_t)(arow * ASTR + achunk * 4) * 4;
        CP_ASYNC16(adst, aptr[p] + achunk * 4);
    }
    const uint32_t sbB = sb + A_BYTES;
    #pragma unroll
    for (int p = 0; p < 8; p++) {
        int brow = (tid >> 5) + p * 4;
        uint32_t bdst = sbB + (uint32_t)(brow * BSTR + bchunk * 4) * 4;
        CP_ASYNC16(bdst, bsrc0 + (size_t)brow * UDIM + bchunk * 4);
    }
}

// ---------------------------------------------------------------------------
// MODE 0: conv stage.  grid (1016 m-tiles, 2 n-tiles).   A=x, out=g_y
// MODE 1: local stage. grid (2 m, 2 n, 504 l).           A=g_y, out=z
// ---------------------------------------------------------------------------
template <int MODE>
__global__ void __launch_bounds__(128, 2)
gemm_mma(const float* __restrict__ Ain, const float* __restrict__ Bmat0,
         const float* __restrict__ bias, const float* __restrict__ gg,
         const float* __restrict__ bbn, const float* __restrict__ mmn,
         const float* __restrict__ vvn, float* __restrict__ outp)
{
    extern __shared__ char smem[];
    const uint32_t sbase = smem_u32(smem);
    const uint32_t sb0 = sbase + SMEM_STAGE0;
    const int tid  = threadIdx.x;
    const int wid  = tid >> 5;
    const int lane = tid & 31;
    const int wm   = wid & 1;          // warp m index (0..1), 64 rows each
    const int wn   = wid >> 1;         // warp n index (0..1), 64 cols each
    const int g    = lane >> 2;
    const int tg   = lane & 3;

    const int S   = MODE ? (KLOC / KC) : (KCONV / KC);
    const int l   = MODE ? blockIdx.z : 0;
    const int mb0 = blockIdx.x * AROWS;
    const int n0  = blockIdx.y * 128;

    const float* Bmat = MODE ? (Bmat0 + (size_t)l * KLOC * UDIM) : Bmat0;
    float* out = MODE ? outp : g_y;

    // BN alpha/beta (alpha carries the tf32-truncation bias correction)
    {
        int n = n0 + tid;
        float a_ = gg[n] * rsqrtf(vvn[n] + BNEPS);
        float bi = MODE ? bias[(size_t)l * UDIM + n] : bias[n];
        ((float*)(smem + SMEM_ALPHA))[tid] = a_ * TCORR;
        ((float*)(smem + SMEM_BETA))[tid]  = bbn[n] + (bi - mmn[n]) * a_;
    }

    // per-thread A row pointers for the 8 load passes
    const float* aptr[8];
    #pragma unroll
    for (int p = 0; p < 8; p++) {
        int r = (tid >> 3) + p * 16;
        if (MODE) {
            aptr[p] = g_y + ((size_t)(mb0 + r) * L1DIM + l) * UDIM;
        } else {
            unsigned gm = mb0 + r;
            unsigned b  = gm / L1DIM;
            unsigned t  = gm - b * L1DIM;
            aptr[p] = Ain + ((size_t)b * LIN + t) * CIN;
        }
    }

    // pipeline prologue: stages 0 and 1
    #pragma unroll
    for (int p = 0; p < NSTAGE - 1; p++) {
        load_stage(sb0 + p * STAGE_BYTES, aptr, Bmat + (size_t)(p * KC) * UDIM + n0, tid);
        #pragma unroll
        for (int i = 0; i < 8; i++) aptr[i] += KC;
        CP_COMMIT();
    }

    float acc[4][8][4] = {};

    // ldmatrix lane->tile-row mapping for A fragments (4 m-frags of 16 rows)
    const int trow = (lane & 7) + ((lane >> 3) & 1) * 8;
    const int tk   = (lane >> 4) * 4;
    int a_lm_off[4];
    #pragma unroll
    for (int mf = 0; mf < 4; mf++)
        a_lm_off[mf] = (wm * 64 + mf * 16 + trow) * ASTR + tk;
    // scalar-B fragment base offset (floats)
    const int boff = tg * BSTR + wn * 64 + g;

    // Loop invariant: stage s = cp.async group s; committed before iter s's
    // wait = 2+s groups, wait_group(1) -> group s resident. The single
    // barrier proves compute s-1 done, protecting slot (s+2)%3 == (s-1)%3
    // for the loads issued right after it.
    for (int s = 0; s < S; s++) {
        CP_WAIT1();
        __syncthreads();

        int pn = s + NSTAGE - 1;
        if (pn < S) {
            load_stage(sb0 + (pn % NSTAGE) * STAGE_BYTES, aptr,
                       Bmat + (size_t)(pn * KC) * UDIM + n0, tid);
            #pragma unroll
            for (int i = 0; i < 8; i++) aptr[i] += KC;
        }
        CP_COMMIT();          // uniform one group per iteration (may be empty)

        const uint32_t stg = sb0 + (s % NSTAGE) * STAGE_BYTES;
        const uint32_t* bB = (const uint32_t*)(smem + SMEM_STAGE0 +
                                               (s % NSTAGE) * STAGE_BYTES +
                                               A_BYTES) + boff;

        #pragma unroll
        for (int k8 = 0; k8 < KC / 8; k8++) {
            const int kk = k8 * 8;
            uint32_t af[4][4];
            #pragma unroll
            for (int mf = 0; mf < 4; mf++)
                ldsm_x4(af[mf], stg + (uint32_t)(a_lm_off[mf] + kk) * 4);
            uint32_t bf[8][2];
            #pragma unroll
            for (int jf = 0; jf < 8; jf++) {
                const uint32_t* p0 = bB + kk * BSTR + jf * 8;
                bf[jf][0] = p0[0];
                bf[jf][1] = p0[4 * BSTR];
            }
            #pragma unroll
            for (int mf = 0; mf < 4; mf++)
                #pragma unroll
                for (int jf = 0; jf < 8; jf++)
                    mma8(acc[mf][jf], af[mf], bf[jf]);
        }
    }

    // ---- epilogue: BN + ReLU, write out ----
    const float* al = (const float*)(smem + SMEM_ALPHA);
    const float* be = (const float*)(smem + SMEM_BETA);
    #pragma unroll
    for (int mf = 0; mf < 4; mf++) {
        int r0 = mb0 + wm * 64 + mf * 16 + g;   // and r0+8
        float* orow0;
        float* orow1;
        if (MODE) {
            orow0 = out + ((size_t)r0 * L2DIM + l) * UDIM;
            orow1 = out + ((size_t)(r0 + 8) * L2DIM + l) * UDIM;
        } else {
            orow0 = out + (size_t)r0 * UDIM;
            orow1 = out + (size_t)(r0 + 8) * UDIM;
        }
        #pragma unroll
        for (int jf = 0; jf < 8; jf++) {
            int cl = wn * 64 + jf * 8 + 2 * tg;
            float a0 = al[cl], a1 = al[cl + 1];
            float e0 = be[cl], e1 = be[cl + 1];
            float2 v0, v1;
            v0.x = fmaxf(acc[mf][jf][0] * a0 + e0, 0.f);
            v0.y = fmaxf(acc[mf][jf][1] * a1 + e1, 0.f);
            v1.x = fmaxf(acc[mf][jf][2] * a0 + e0, 0.f);
            v1.y = fmaxf(acc[mf][jf][3] * a1 + e1, 0.f);
            *(float2*)(orow0 + n0 + cl) = v0;
            *(float2*)(orow1 + n0 + cl) = v1;
        }
    }
}

// ---------------------------------------------------------------------------
extern "C" void kernel_launch(void* const* d_in, const int* in_sizes, int n_in,
                              void* d_out, int out_size)
{
    const float* x      = (const float*)d_in[0];
    const float* conv_w = (const float*)d_in[1];
    const float* conv_b = (const float*)d_in[2];
    const float* g1     = (const float*)d_in[3];
    const float* b1     = (const float*)d_in[4];
    const float* m1     = (const float*)d_in[5];
    const float* v1     = (const float*)d_in[6];
    const float* lw     = (const float*)d_in[7];
    const float* lb     = (const float*)d_in[8];
    const float* g2     = (const float*)d_in[9];
    const float* b2     = (const float*)d_in[10];
    const float* m2     = (const float*)d_in[11];
    const float* v2     = (const float*)d_in[12];
    float* z = (float*)d_out;

    static bool attr_set = false;
    if (!attr_set) {
        cudaFuncSetAttribute(gemm_mma<0>,
            cudaFuncAttributeMaxDynamicSharedMemorySize, SMEM_TOTAL);
        cudaFuncSetAttribute(gemm_mma<1>,
            cudaFuncAttributeMaxDynamicSharedMemorySize, SMEM_TOTAL);
        cudaFuncSetAttribute(gemm_mma<0>,
            cudaFuncAttributePreferredSharedMemoryCarveout, 100);
        cudaFuncSetAttribute(gemm_mma<1>,
            cudaFuncAttributePreferredSharedMemoryCarveout, 100);
        attr_set = true;
    }

    // Stage 1: M=130048 (1016 tiles of 128), N=256 (2 tiles), K=320
    gemm_mma<0><<<dim3(1016, 2, 1), 128, SMEM_TOTAL>>>(
        x, conv_w, conv_b, g1, b1, m1, v1, nullptr);

    // Stage 2: per-l GEMMs, M=256 (2 tiles), N=256 (2 tiles), K=1280, l=504
    gemm_mma<1><<<dim3(2, 2, L2DIM), 128, SMEM_TOTAL>>>(
        nullptr, lw, lb, g2, b2, m2, v2, z);
}

// round 15
// speedup vs baseline: 1.2138x; 1.1338x over previous
#include <cuda_runtime.h>
#include <cstdint>

// ---------------------------------------------------------------------------
// ConvLocalBlock via legacy mma.sync.m16n8k8 tf32 (PTX compute_103-safe; the
// harness's PTX target has no 'a' suffix so tcgen05/TMEM are unavailable).
//
// Stage 1: y = relu(bn1(x_patches @ conv_w))      M=130048 K=320  N=256
// Stage 2: z[:,l,:] = relu(bn2(y_win @ lw[l]))    per l: M=256 K=1280 N=256
//
// R14 = R13's register double-buffering with the R12 barrier ordering
// restored. R13's rel_err 2.1e-2 was a visibility race: cp.async.wait_group
// only covers the waiting thread's own copies; reading other threads' tiles
// requires a __syncthreads AFTER the wait. Loop is now:
//   wait_group(0)   -> stages s and s+1 resident (group s+1 issued a full
//                      compute-stage ago, so this wait is ~free)
//   __syncthreads() -> cross-thread visibility + proves compute s-1 done
//                      (WAR cover for this iter's load target slot (s+2)%3)
//   issue loads s+2; commit
//   compute s, prefetching k8+1 fragments (tail: stage s+1 k8=0 from slot
//   (s+1)%3, which nothing writes during iter s) into the alternate register
//   buffer -> first HMMA after every barrier has zero fill latency.
//
// Geometry: CTA 128x128, 4 warps (2m x 2n of 64x64), NSTAGE=3 cp.async ring,
// 2 CTAs/SM. Engine: raw-fp32-bits tf32 MMA (RZ truncation, product bias
// cancelled by TCORR in BN alpha), A via ldmatrix.x4.b16, B scalar LDS with
// BSTR=136 (conflict-free).
// ---------------------------------------------------------------------------

#define FSZ   5
#define NB    256
#define LIN   512
#define CIN   64
#define UDIM  256
#define L1DIM 508
#define L2DIM 504
#define KCONV 320
#define KLOC  1280
#define BNEPS 0.001f
#define TCORR 1.0007045f              // cancels tf32 RZ-truncation product bias

#define NSTAGE  3
#define KC      32
#define AROWS   128                   // CTA M-tile
#define ASTR    36                    // A smem row stride (floats)
#define BSTR    136                   // B smem row stride (136%32==8: clean)
#define A_BYTES (AROWS * ASTR * 4)    // 18432
#define B_BYTES (KC * BSTR * 4)       // 17408
#define STAGE_BYTES (A_BYTES + B_BYTES) // 35840
#define SMEM_ALPHA  0
#define SMEM_BETA   512
#define SMEM_STAGE0 1024
#define SMEM_TOTAL  (SMEM_STAGE0 + NSTAGE * STAGE_BYTES)  // 108544 (106 KB)

__device__ __align__(128) float g_y[(size_t)NB * L1DIM * UDIM];

// ---- PTX helpers -----------------------------------------------------------
__device__ __forceinline__ uint32_t smem_u32(const void* p) {
    uint32_t a;
    asm("{ .reg .u64 t; cvta.to.shared.u64 t, %1; cvt.u32.u64 %0, t; }"
        : "=r"(a) : "l"(p));
    return a;
}
#define CP_ASYNC16(dst, src) \
    asm volatile("cp.async.cg.shared.global [%0], [%1], 16;" \
                 :: "r"(dst), "l"(src) : "memory")
#define CP_COMMIT() asm volatile("cp.async.commit_group;" ::: "memory")
#define CP_WAIT0()  asm volatile("cp.async.wait_group 0;" ::: "memory")
#define CP_WAIT1()  asm volatile("cp.async.wait_group 1;" ::: "memory")

__device__ __forceinline__ void ldsm_x4(uint32_t* r, uint32_t addr) {
    asm volatile("ldmatrix.sync.aligned.m8n8.x4.shared.b16 {%0,%1,%2,%3}, [%4];"
                 : "=r"(r[0]), "=r"(r[1]), "=r"(r[2]), "=r"(r[3]) : "r"(addr));
}
__device__ __forceinline__ void mma8(float* d, const uint32_t* a, const uint32_t* b) {
    asm volatile("mma.sync.aligned.m16n8k8.row.col.f32.tf32.tf32.f32 "
                 "{%0,%1,%2,%3}, {%4,%5,%6,%7}, {%8,%9}, {%0,%1,%2,%3};"
                 : "+f"(d[0]), "+f"(d[1]), "+f"(d[2]), "+f"(d[3])
                 : "r"(a[0]), "r"(a[1]), "r"(a[2]), "r"(a[3]),
                   "r"(b[0]), "r"(b[1]));
}

// one pipeline-stage load (128 threads): A 128 rows x 32 floats + B 32 x 128
__device__ __forceinline__ void load_stage(uint32_t sb, const float* const* aptr,
                                           const float* bsrc0, int tid) {
    const int achunk = tid & 7;
    const int bchunk = tid & 31;
    #pragma unroll
    for (int p = 0; p < 8; p++) {
        int arow = (tid >> 3) + p * 16;
        uint32_t adst = sb + (uint32_t)(arow * ASTR + achunk * 4) * 4;
        CP_ASYNC16(adst, aptr[p] + achunk * 4);
    }
    const uint32_t sbB = sb + A_BYTES;
    #pragma unroll
    for (int p = 0; p < 8; p++) {
        int brow = (tid >> 5) + p * 4;
        uint32_t bdst = sbB + (uint32_t)(brow * BSTR + bchunk * 4) * 4;
        CP_ASYNC16(bdst, bsrc0 + (size_t)brow * UDIM + bchunk * 4);
    }
}

// ---------------------------------------------------------------------------
// MODE 0: conv stage.  grid (1016 m-tiles, 2 n-tiles).   A=x, out=g_y
// MODE 1: local stage. grid (2 m, 2 n, 504 l).           A=g_y, out=z
// ---------------------------------------------------------------------------
template <int MODE>
__global__ void __launch_bounds__(128, 2)
gemm_mma(const float* __restrict__ Ain, const float* __restrict__ Bmat0,
         const float* __restrict__ bias, const float* __restrict__ gg,
         const float* __restrict__ bbn, const float* __restrict__ mmn,
         const float* __restrict__ vvn, float* __restrict__ outp)
{
    extern __shared__ char smem[];
    const uint32_t sbase = smem_u32(smem);
    const uint32_t sb0 = sbase + SMEM_STAGE0;
    const int tid  = threadIdx.x;
    const int wid  = tid >> 5;
    const int lane = tid & 31;
    const int wm   = wid & 1;          // warp m index (0..1), 64 rows each
    const int wn   = wid >> 1;         // warp n index (0..1), 64 cols each
    const int g    = lane >> 2;
    const int tg   = lane & 3;

    const int S   = MODE ? (KLOC / KC) : (KCONV / KC);
    const int l   = MODE ? blockIdx.z : 0;
    const int mb0 = blockIdx.x * AROWS;
    const int n0  = blockIdx.y * 128;

    const float* Bmat = MODE ? (Bmat0 + (size_t)l * KLOC * UDIM) : Bmat0;
    float* out = MODE ? outp : g_y;

    // BN alpha/beta (alpha carries the tf32-truncation bias correction)
    {
        int n = n0 + tid;
        float a_ = gg[n] * rsqrtf(vvn[n] + BNEPS);
        float bi = MODE ? bias[(size_t)l * UDIM + n] : bias[n];
        ((float*)(smem + SMEM_ALPHA))[tid] = a_ * TCORR;
        ((float*)(smem + SMEM_BETA))[tid]  = bbn[n] + (bi - mmn[n]) * a_;
    }

    // per-thread A row pointers for the 8 load passes
    const float* aptr[8];
    #pragma unroll
    for (int p = 0; p < 8; p++) {
        int r = (tid >> 3) + p * 16;
        if (MODE) {
            aptr[p] = g_y + ((size_t)(mb0 + r) * L1DIM + l) * UDIM;
        } else {
            unsigned gm = mb0 + r;
            unsigned b  = gm / L1DIM;
            unsigned t  = gm - b * L1DIM;
            aptr[p] = Ain + ((size_t)b * LIN + t) * CIN;
        }
    }

    // pipeline prologue: stages 0 and 1 (groups 0, 1)
    #pragma unroll
    for (int p = 0; p < NSTAGE - 1; p++) {
        load_stage(sb0 + p * STAGE_BYTES, aptr, Bmat + (size_t)(p * KC) * UDIM + n0, tid);
        #pragma unroll
        for (int i = 0; i < 8; i++) aptr[i] += KC;
        CP_COMMIT();
    }

    float acc[4][8][4] = {};

    // ldmatrix lane->tile-row mapping for A fragments (4 m-frags of 16 rows)
    const int trow = (lane & 7) + ((lane >> 3) & 1) * 8;
    const int tk   = (lane >> 4) * 4;
    int a_lm_off[4];
    #pragma unroll
    for (int mf = 0; mf < 4; mf++)
        a_lm_off[mf] = (wm * 64 + mf * 16 + trow) * ASTR + tk;
    const int boff = tg * BSTR + wn * 64 + g;   // B fragment base (floats)

    // double-buffered fragments; buffer index = k8&1 (compile-time)
    uint32_t af[2][4][4];
    uint32_t bf[2][8][2];

    auto frags = [&](int d, uint32_t stg, const uint32_t* bB, int kk) {
        #pragma unroll
        for (int mf = 0; mf < 4; mf++)
            ldsm_x4(af[d][mf], stg + (uint32_t)(a_lm_off[mf] + kk) * 4);
        #pragma unroll
        for (int jf = 0; jf < 8; jf++) {
            const uint32_t* p0 = bB + kk * BSTR + jf * 8;
            bf[d][jf][0] = p0[0];
            bf[d][jf][1] = p0[4 * BSTR];
        }
    };

    // pre-loop: make stage 0 visible, prime buffer 0 with (stage 0, k8=0)
    CP_WAIT1();
    __syncthreads();
    {
        const uint32_t* bB0 = (const uint32_t*)(smem + SMEM_STAGE0 + A_BYTES) + boff;
        frags(0, sb0, bB0, 0);
    }

    // Main loop invariant at iter s:
    //   committed groups before this iter = 0..s+1 (prologue 2 + one/iter).
    //   wait_group(0) -> stages s and s+1 complete; the following barrier
    //   publishes them cross-thread AND proves compute s-1 done in all warps,
    //   covering the WAR on this iter's load target slot (s+2)%3 == (s-1)%3.
    //   Tail prefetch reads slot (s+1)%3, which no load writes during iter s.
    for (int s = 0; s < S; s++) {
        CP_WAIT0();
        __syncthreads();

        int pn = s + NSTAGE - 1;
        if (pn < S) {
            load_stage(sb0 + (pn % NSTAGE) * STAGE_BYTES, aptr,
                       Bmat + (size_t)(pn * KC) * UDIM + n0, tid);
            #pragma unroll
            for (int i = 0; i < 8; i++) aptr[i] += KC;
        }
        CP_COMMIT();          // uniform one group per iteration (may be empty)

        const uint32_t stgS  = sb0 + (s % NSTAGE) * STAGE_BYTES;
        const uint32_t stgS1 = sb0 + ((s + 1) % NSTAGE) * STAGE_BYTES;
        const uint32_t* bBS  = (const uint32_t*)(smem + SMEM_STAGE0 +
                               (s % NSTAGE) * STAGE_BYTES + A_BYTES) + boff;
        const uint32_t* bBS1 = (const uint32_t*)(smem + SMEM_STAGE0 +
                               ((s + 1) % NSTAGE) * STAGE_BYTES + A_BYTES) + boff;

        #pragma unroll
        for (int k8 = 0; k8 < KC / 8; k8++) {
            const int cur = k8 & 1;
            const int nxt = cur ^ 1;
            if (k8 < KC / 8 - 1) {
                frags(nxt, stgS, bBS, (k8 + 1) * 8);
            } else if (s + 1 < S) {
                frags(nxt, stgS1, bBS1, 0);   // stage s+1 visible since this
                                              // iter's wait0+sync; slot safe
            }
            #pragma unroll
            for (int mf = 0; mf < 4; mf++)
                #pragma unroll
                for (int jf = 0; jf < 8; jf++)
                    mma8(acc[mf][jf], af[cur][mf], bf[cur][jf]);
        }
    }

    // ---- epilogue: BN + ReLU, write out ----
    const float* al = (const float*)(smem + SMEM_ALPHA);
    const float* be = (const float*)(smem + SMEM_BETA);
    #pragma unroll
    for (int mf = 0; mf < 4; mf++) {
        int r0 = mb0 + wm * 64 + mf * 16 + g;   // and r0+8
        float* orow0;
        float* orow1;
        if (MODE) {
            orow0 = out + ((size_t)r0 * L2DIM + l) * UDIM;
            orow1 = out + ((size_t)(r0 + 8) * L2DIM + l) * UDIM;
        } else {
            orow0 = out + (size_t)r0 * UDIM;
            orow1 = out + (size_t)(r0 + 8) * UDIM;
        }
        #pragma unroll
        for (int jf = 0; jf < 8; jf++) {
            int cl = wn * 64 + jf * 8 + 2 * tg;
            float a0 = al[cl], a1 = al[cl + 1];
            float e0 = be[cl], e1 = be[cl + 1];
            float2 v0, v1;
            v0.x = fmaxf(acc[mf][jf][0] * a0 + e0, 0.f);
            v0.y = fmaxf(acc[mf][jf][1] * a1 + e1, 0.f);
            v1.x = fmaxf(acc[mf][jf][2] * a0 + e0, 0.f);
            v1.y = fmaxf(acc[mf][jf][3] * a1 + e1, 0.f);
            *(float2*)(orow0 + n0 + cl) = v0;
            *(float2*)(orow1 + n0 + cl) = v1;
        }
    }
}

// ---------------------------------------------------------------------------
extern "C" void kernel_launch(void* const* d_in, const int* in_sizes, int n_in,
                              void* d_out, int out_size)
{
    const float* x      = (const float*)d_in[0];
    const float* conv_w = (const float*)d_in[1];
    const float* conv_b = (const float*)d_in[2];
    const float* g1     = (const float*)d_in[3];
    const float* b1     = (const float*)d_in[4];
    const float* m1     = (const float*)d_in[5];
    const float* v1     = (const float*)d_in[6];
    const float* lw     = (const float*)d_in[7];
    const float* lb     = (const float*)d_in[8];
    const float* g2     = (const float*)d_in[9];
    const float* b2     = (const float*)d_in[10];
    const float* m2     = (const float*)d_in[11];
    const float* v2     = (const float*)d_in[12];
    float* z = (float*)d_out;

    static bool attr_set = false;
    if (!attr_set) {
        cudaFuncSetAttribute(gemm_mma<0>,
            cudaFuncAttributeMaxDynamicSharedMemorySize, SMEM_TOTAL);
        cudaFuncSetAttribute(gemm_mma<1>,
            cudaFuncAttributeMaxDynamicSharedMemorySize, SMEM_TOTAL);
        cudaFuncSetAttribute(gemm_mma<0>,
            cudaFuncAttributePreferredSharedMemoryCarveout, 100);
        cudaFuncSetAttribute(gemm_mma<1>,
            cudaFuncAttributePreferredSharedMemoryCarveout, 100);
        attr_set = true;
    }

    // Stage 1: M=130048 (1016 tiles of 128), N=256 (2 tiles), K=320
    gemm_mma<0><<<dim3(1016, 2, 1), 128, SMEM_TOTAL>>>(
        x, conv_w, conv_b, g1, b1, m1, v1, nullptr);

    // Stage 2: per-l GEMMs, M=256 (2 tiles), N=256 (2 tiles), K=1280, l=504
    gemm_mma<1><<<dim3(2, 2, L2DIM), 128, SMEM_TOTAL>>>(
        nullptr, lw, lb, g2, b2, m2, v2, z);
}